// round 9
// baseline (speedup 1.0000x reference)
#include <cuda_runtime.h>
#include <cuda_fp16.h>
#include <math.h>
#include <stdint.h>

// Problem constants
#define BB   64
#define NN   1024
#define DD   256
#define HH   256
#define G3   768            // 3*H
#define NB   (BB*NN)        // 65536 rows
#define TG   32             // rows per group in seq kernel
#define SEQ_CTAS 148
#define PITCH 264           // fp16 pitch for A smem tiles (132 u32; LDSM conflict-free)

// ---------------- scratch (device globals) ------------------------------------
__device__ float g_gi  [NB*G3];                 // input gates (192 MB)
__device__ float g_h   [NB*HH];                 // hidden states (64 MB)
__device__ __half g_x_h[NB*DD];                 // fp16 activations
// hi-only frag-packed weights: [n][ks][tq] -> uint2 {hi0, hi1}
__device__ __align__(16) uint2 g_wih_h2[G3*64];
__device__ __align__(16) uint2 g_whh_h2[G3*64];
__device__ unsigned short g_depth[NB];
__device__ int   g_cnt    [BB*NN];
__device__ int   g_rbstart[BB*NN];
__device__ int   g_rptr   [NN+1];
__device__ int   g_sched  [NB];
__device__ int   g_maxd;
__device__ unsigned g_bar_count = 0;
__device__ unsigned g_bar_gen   = 0;

// ---------------- helpers ------------------------------------------------------
// NOTE: non-volatile on purpose — pure op, lets ptxas software-pipeline/interleave.
__device__ __forceinline__ void mma16816(float* c,
        uint32_t a0, uint32_t a1, uint32_t a2, uint32_t a3,
        uint32_t b0, uint32_t b1) {
    asm("mma.sync.aligned.m16n8k16.row.col.f32.f16.f16.f32 "
        "{%0,%1,%2,%3}, {%4,%5,%6,%7}, {%8,%9}, {%0,%1,%2,%3};"
        : "+f"(c[0]), "+f"(c[1]), "+f"(c[2]), "+f"(c[3])
        : "r"(a0), "r"(a1), "r"(a2), "r"(a3), "r"(b0), "r"(b1));
}
__device__ __forceinline__ void ldsm4(uint32_t addr, uint32_t* r) {
    asm volatile("ldmatrix.sync.aligned.m8n8.x4.shared.b16 {%0,%1,%2,%3}, [%4];"
        : "=r"(r[0]), "=r"(r[1]), "=r"(r[2]), "=r"(r[3]) : "r"(addr));
}
__device__ __forceinline__ uint32_t smem_u32(const void* p) {
    uint32_t a;
    asm("{ .reg .u64 t; cvta.to.shared.u64 t, %1; cvt.u32.u64 %0, t; }" : "=r"(a) : "l"(p));
    return a;
}
__device__ __forceinline__ uint32_t pack_h2(float x, float y) {
    __half2 h = __floats2half2_rn(x, y);
    return *reinterpret_cast<uint32_t*>(&h);
}
__device__ __forceinline__ float sigm(float x) { return 1.0f / (1.0f + expf(-x)); }

// ---------------- prep: frag-pack weights (hi-only, both matrices) -------------
__global__ void prep_kernel(const float* __restrict__ wih,
                            const float* __restrict__ whh) {
    int e = blockIdx.x * blockDim.x + threadIdx.x;   // 0..49151
    if (e == 0) g_maxd = 0;
    if (e >= G3*64) return;
    int n  = e >> 6;
    int r  = e & 63;
    int ks = r >> 2, tq = r & 3;
    int p  = ks*8 + tq;
    int k0 = 2*p;
    {
        uint2 v;
        v.x = pack_h2(wih[n*256 + k0],     wih[n*256 + k0 + 1]);
        v.y = pack_h2(wih[n*256 + k0 + 8], wih[n*256 + k0 + 9]);
        g_wih_h2[e] = v;
    }
    {
        uint2 v;
        v.x = pack_h2(whh[n*256 + k0],     whh[n*256 + k0 + 1]);
        v.y = pack_h2(whh[n*256 + k0 + 8], whh[n*256 + k0 + 9]);
        g_whh_h2[e] = v;
    }
}

// ---------------- embeddings + first half of output ----------------------------
__global__ void embed_kernel(const int* __restrict__ node_types,
                             const int* __restrict__ node_vals,
                             const int* __restrict__ child_positions,
                             const float* __restrict__ type_emb,
                             const float* __restrict__ pos_table,
                             const float* __restrict__ token_emb,
                             float* __restrict__ out) {
    int id  = blockIdx.x;
    int tid = threadIdx.x;
    int b = id >> 10, n = id & 1023;
    int tt = node_types[id];
    int cp = child_positions[id];
    int v0 = node_vals[2*id];
    int v1 = node_vals[2*id + 1];
    float x = type_emb[tt*DD + tid] * 4.0f + pos_table[cp*DD + tid] * 0.25f;
    float tok = token_emb[v0*DD + tid] + token_emb[v1*DD + tid];
    g_x_h[id*DD + tid] = __float2half(x);
    out[((n*BB + b) * (DD+HH)) + tid] = x + tok * 2.0f;
}

// ---------------- GI GEMM: 512 threads, M=128/CTA, 3 N-chunks, single fp16 term
#define GI_SMEM (128 * PITCH * 2)   // fp16 A tile, bytes

__global__ void __launch_bounds__(512, 1) gi_mma_kernel(const float* __restrict__ bih) {
    extern __shared__ __half sA[];              // [128][PITCH]
    int tid = threadIdx.x;
    int wid = tid >> 5, lane = tid & 31;
    int gid = lane >> 2, tq = lane & 3;
    int wm = wid >> 3, wc = wid & 7;
    long row0 = (long)blockIdx.x * 128;

    // fill A: 128 rows x 128 u32
    {
        const uint32_t* src = (const uint32_t*)g_x_h + row0 * 128;
        uint32_t* dst = (uint32_t*)sA;
        for (int idx = tid; idx < 128 * 128; idx += 512) {
            int m = idx >> 7, j = idx & 127;
            dst[m * (PITCH/2) + j] = src[idx];
        }
    }
    __syncthreads();

    int l7 = lane & 7, q = lane >> 3;
    uint32_t aoff = (((q & 1) * 8 + l7) * (PITCH/2) + (q >> 1) * 4) * 4;
    uint32_t sAA = smem_u32(sA);
    uint32_t ad[4];
    #pragma unroll
    for (int mt = 0; mt < 4; mt++)
        ad[mt] = sAA + (wm * 64 + mt * 16) * (PITCH*2) + aoff;

    for (int c = 0; c < 3; c++) {
        float C[4][4][4];
        #pragma unroll
        for (int mt = 0; mt < 4; mt++)
            #pragma unroll
            for (int nt = 0; nt < 4; nt++)
                #pragma unroll
                for (int qq = 0; qq < 4; qq++) C[mt][nt][qq] = 0.0f;

        #pragma unroll 2
        for (int ks = 0; ks < 16; ks++) {
            uint32_t aF[4][4];
            #pragma unroll
            for (int mt = 0; mt < 4; mt++) ldsm4(ad[mt] + ks * 32, aF[mt]);
            uint2 bw[4];
            #pragma unroll
            for (int nt = 0; nt < 4; nt++) {
                int n = c * 256 + wc * 32 + nt * 8 + gid;
                bw[nt] = g_wih_h2[n * 64 + ks * 4 + tq];
            }
            #pragma unroll
            for (int nt = 0; nt < 4; nt++)
                #pragma unroll
                for (int mt = 0; mt < 4; mt++)
                    mma16816(C[mt][nt], aF[mt][0], aF[mt][1], aF[mt][2], aF[mt][3],
                             bw[nt].x, bw[nt].y);
        }
        // epilogue: add bias, store fp32
        #pragma unroll
        for (int mt = 0; mt < 4; mt++) {
            long r = row0 + wm * 64 + mt * 16 + gid;
            #pragma unroll
            for (int nt = 0; nt < 4; nt++) {
                int col = c * 256 + wc * 32 + nt * 8 + tq * 2;
                float2 bv = *(const float2*)(bih + col);
                float2 v0 = make_float2(C[mt][nt][0] + bv.x, C[mt][nt][1] + bv.y);
                float2 v1 = make_float2(C[mt][nt][2] + bv.x, C[mt][nt][3] + bv.y);
                *(float2*)(g_gi + r * G3 + col)       = v0;
                *(float2*)(g_gi + (r + 8) * G3 + col) = v1;
            }
        }
    }
}

// ---------------- scheduler S1: parallel pointer-doubling depths ---------------
__global__ void __launch_bounds__(256) sched1_kernel(const int* __restrict__ lpi) {
    __shared__ int            jb[NN];
    __shared__ unsigned short db[NN];
    __shared__ int            scnt[NN];
    __shared__ int            smax;
    int b = blockIdx.x, tid = threadIdx.x;
    if (tid == 0) smax = 0;
    for (int i = tid; i < NN; i += 256) {
        jb[i] = (i == 0) ? 0 : lpi[b*NN + i];
        db[i] = (i == 0) ? 0 : 1;
        scnt[i] = 0;
    }
    __syncthreads();
    #pragma unroll 1
    for (int s = 0; s < 10; s++) {
        int nd[4], nj[4];
        #pragma unroll
        for (int u = 0; u < 4; u++) {
            int i = tid + u * 256;
            int j = jb[i];
            nd[u] = db[i] + db[j];
            nj[u] = jb[j];
        }
        __syncthreads();
        #pragma unroll
        for (int u = 0; u < 4; u++) {
            int i = tid + u * 256;
            db[i] = (unsigned short)nd[u];
            jb[i] = nj[u];
        }
        __syncthreads();
    }
    int lm = 0;
    for (int i = tid; i < NN; i += 256) {
        atomicAdd(&scnt[db[i]], 1);
        lm = max(lm, (int)db[i]);
    }
    atomicMax(&smax, lm);
    __syncthreads();
    if (tid == 0) atomicMax(&g_maxd, smax);
    for (int i = tid; i < NN; i += 256) {
        g_depth[b*NN + i] = db[i];
        g_cnt  [b*NN + i] = scnt[i];
    }
}

// ---------------- scheduler S2 -------------------------------------------------
__global__ void __launch_bounds__(1024) sched2_kernel() {
    __shared__ int stot[NN];
    __shared__ int srptr[NN+1];
    int r = threadIdx.x;
    int s = 0;
    for (int b = 0; b < BB; b++) {
        g_rbstart[b*NN + r] = s;
        s += g_cnt[b*NN + r];
    }
    stot[r] = s;
    __syncthreads();
    if (r == 0) {
        int acc = 0;
        for (int i = 0; i < NN; i++) { srptr[i] = acc; acc += stot[i]; }
        srptr[NN] = acc;
    }
    __syncthreads();
    for (int b = 0; b < BB; b++) g_rbstart[b*NN + r] += srptr[r];
    g_rptr[r] = srptr[r];
    if (r == 0) g_rptr[NN] = srptr[NN];
}

// ---------------- scheduler S3: parallel scatter -------------------------------
__global__ void __launch_bounds__(256) sched3_kernel() {
    __shared__ int scur[NN];
    int b = blockIdx.x, tid = threadIdx.x;
    for (int i = tid; i < NN; i += 256) scur[i] = g_rbstart[b*NN + i];
    __syncthreads();
    for (int i = tid; i < NN; i += 256) {
        int d = g_depth[b*NN + i];
        int pos = atomicAdd(&scur[d], 1);
        g_sched[pos] = (b << 10) | i;
    }
}

// ---------------- persistent level-parallel GRU (mma.sync, 512 thr) ------------
__device__ __forceinline__ void grid_barrier() {
    __threadfence();
    __syncthreads();
    if (threadIdx.x == 0) {
        unsigned gen = *(volatile unsigned*)&g_bar_gen;
        if (atomicAdd(&g_bar_count, 1u) == (unsigned)gridDim.x - 1u) {
            g_bar_count = 0u;
            __threadfence();
            *(volatile unsigned*)&g_bar_gen = gen + 1u;
        } else {
            while (*(volatile unsigned*)&g_bar_gen == gen) { __nanosleep(64); }
        }
        __threadfence();
    }
    __syncthreads();
}

// Column-split groups: each (rows-group, half) pair is one work unit.
// Half h owns output cols [h*128, h*128+128). Warp wid (0..15) owns base col
// cp = h*128 + 8*wid; gate triplet n-tiles: n = jj*256 + h*128 + 8*wid, jj=0..2.
__global__ void __launch_bounds__(512, 1) seq_kernel(const int* __restrict__ lpi,
                                                     const float* __restrict__ bhh,
                                                     float* __restrict__ out) {
    __shared__ __half sH[TG * PITCH];
    __shared__ int sMeta[TG];
    __shared__ int sPar[TG];
    int tid = threadIdx.x;
    int wid = tid >> 5, lane = tid & 31;
    int gid = lane >> 2, tq = lane & 3;
    int maxd = g_maxd;

    uint32_t* dH = (uint32_t*)sH;

    int l7 = lane & 7, q = lane >> 3;
    uint32_t aoff = (((q & 1) * 8 + l7) * (PITCH/2) + (q >> 1) * 4) * 4;
    uint32_t sHA = smem_u32(sH);
    uint32_t ad[2];
    #pragma unroll
    for (int mt = 0; mt < 2; mt++)
        ad[mt] = sHA + (mt * 16) * (PITCH*2) + aoff;

    for (int r = 0; r <= maxd; r++) {
        int start = g_rptr[r];
        int cnt   = g_rptr[r+1] - start;
        int nrow_groups = (cnt + TG - 1) / TG;
        int nunits = nrow_groups * 2;              // column-split x2
        for (int u = blockIdx.x; u < nunits; u += gridDim.x) {
            int gidx = u >> 1;
            int half = u & 1;
            int t0 = start + gidx * TG;
            int tc = cnt - gidx * TG; if (tc > TG) tc = TG;
            if (tid < TG) {
                if (tid < tc) {
                    int s = g_sched[t0 + tid];
                    sMeta[tid] = s;
                    int b = s >> 10, i = s & 1023;
                    sPar[tid] = (i == 0) ? -1 : ((b << 10) | lpi[b*NN + i]);
                } else { sMeta[tid] = 0; sPar[tid] = -1; }
            }
            __syncthreads();
            // gather parents -> fp16 smem (full K range; both halves duplicate)
            for (int idx = tid; idx < TG * 64; idx += 512) {
                int t = idx >> 6, k4 = idx & 63;
                int pr = sPar[t];
                float4 v;
                if (pr < 0) { v.x=v.y=v.z=v.w=0.f; }
                else        { v = ((const float4*)&g_h[(long)pr*HH])[k4]; }
                int o = t * (PITCH/2) + k4 * 2;
                dH[o]   = pack_h2(v.x, v.y);
                dH[o+1] = pack_h2(v.z, v.w);
            }
            __syncthreads();

            float C[2][3][4];
            #pragma unroll
            for (int mt = 0; mt < 2; mt++)
                #pragma unroll
                for (int jj = 0; jj < 3; jj++)
                    #pragma unroll
                    for (int qq = 0; qq < 4; qq++) C[mt][jj][qq] = 0.0f;

            int nbase = half * 128 + 8 * wid;
            #pragma unroll 2
            for (int ks = 0; ks < 16; ks++) {
                uint32_t aF[2][4];
                #pragma unroll
                for (int mt = 0; mt < 2; mt++) ldsm4(ad[mt] + ks * 32, aF[mt]);
                uint2 bw[3];
                #pragma unroll
                for (int jj = 0; jj < 3; jj++) {
                    int n = jj * 256 + nbase + gid;
                    bw[jj] = g_whh_h2[n * 64 + ks * 4 + tq];
                }
                #pragma unroll
                for (int jj = 0; jj < 3; jj++)
                    #pragma unroll
                    for (int mt = 0; mt < 2; mt++)
                        mma16816(C[mt][jj], aF[mt][0], aF[mt][1], aF[mt][2], aF[mt][3],
                                 bw[jj].x, bw[jj].y);
            }

            // fused GRU epilogue: one base col per warp
            {
                int cp = nbase + tq * 2;              // output col in [0,256)
                float2 br = *(const float2*)(bhh + cp);
                float2 bz = *(const float2*)(bhh + 256 + cp);
                float2 bn = *(const float2*)(bhh + 512 + cp);
                #pragma unroll
                for (int mt = 0; mt < 2; mt++) {
                    #pragma unroll
                    for (int rh = 0; rh < 2; rh++) {
                        int lr = mt * 16 + gid + rh * 8;
                        if (lr >= tc) continue;
                        float cr0 = C[mt][0][rh*2], cr1 = C[mt][0][rh*2+1];
                        float cz0 = C[mt][1][rh*2], cz1 = C[mt][1][rh*2+1];
                        float cn0 = C[mt][2][rh*2], cn1 = C[mt][2][rh*2+1];
                        int s = sMeta[lr];
                        long row = (long)s;
                        int b = s >> 10, i = s & 1023;
                        const float* gp = g_gi + row * G3;
                        float2 gr = *(const float2*)(gp + cp);
                        float2 gz = *(const float2*)(gp + 256 + cp);
                        float2 gn = *(const float2*)(gp + 512 + cp);
                        int pr = sPar[lr];
                        float hp0, hp1;
                        if (pr < 0) { hp0 = 0.f; hp1 = 0.f; }
                        else {
                            float2 hv = *(const float2*)(g_h + (long)pr * HH + cp);
                            hp0 = hv.x; hp1 = hv.y;
                        }
                        float rg0 = sigm(gr.x + cr0 + br.x);
                        float rg1 = sigm(gr.y + cr1 + br.y);
                        float zg0 = sigm(gz.x + cz0 + bz.x);
                        float zg1 = sigm(gz.y + cz1 + bz.y);
                        float ng0 = tanhf(gn.x + (cn0 + bn.x) * rg0);
                        float ng1 = tanhf(gn.y + (cn1 + bn.y) * rg1);
                        float h0 = (1.0f - zg0) * ng0 + zg0 * hp0;
                        float h1 = (1.0f - zg1) * ng1 + zg1 * hp1;
                        *(float2*)(g_h + row * HH + cp) = make_float2(h0, h1);
                        *(float2*)(out + ((long)(i*BB + b) * (DD+HH)) + DD + cp) = make_float2(h0, h1);
                    }
                }
            }
            __syncthreads();
        }
        grid_barrier();
    }
}

// ---------------- launch -------------------------------------------------------
extern "C" void kernel_launch(void* const* d_in, const int* in_sizes, int n_in,
                              void* d_out, int out_size) {
    const int*   node_types      = (const int*)  d_in[0];
    const int*   node_vals       = (const int*)  d_in[1];
    const int*   last_parent     = (const int*)  d_in[3];
    const int*   child_positions = (const int*)  d_in[4];
    const float* type_emb        = (const float*)d_in[5];
    const float* pos_table       = (const float*)d_in[6];
    const float* token_emb       = (const float*)d_in[7];
    const float* w_ih            = (const float*)d_in[8];
    const float* w_hh            = (const float*)d_in[9];
    const float* b_ih            = (const float*)d_in[10];
    const float* b_hh            = (const float*)d_in[11];
    float* out = (float*)d_out;

    cudaFuncSetAttribute(gi_mma_kernel, cudaFuncAttributeMaxDynamicSharedMemorySize, GI_SMEM);

    prep_kernel<<<192, 256>>>(w_ih, w_hh);
    embed_kernel<<<NB, 256>>>(node_types, node_vals, child_positions,
                              type_emb, pos_table, token_emb, out);
    gi_mma_kernel<<<NB/128, 512, GI_SMEM>>>(b_ih);
    sched1_kernel<<<BB, 256>>>(last_parent);
    sched2_kernel<<<1, 1024>>>();
    sched3_kernel<<<BB, 256>>>();
    seq_kernel<<<SEQ_CTAS, 512>>>(last_parent, b_hh, out);
}